// round 11
// baseline (speedup 1.0000x reference)
#include <cuda_runtime.h>
#include <cstdint>

// T = 2000 tags, V = 20000 videos, D = 768, E_POS = E_NEG = 100000
// Output layout: [cls_score (V*T f32), labels (V*T f32)], row = video.
//
// R11: fused-by-video with L2 cache-priority hints (compile-fixed).
//   K1 scatter_kernel : bin edges by VIDEO (atomic cursors), enc = tag|isPos
//   K2 fused_kernel   : one block per video row.
//      - tag-row gathers : ld.global.nc.L2::evict_last.v4.b64 (32B form —
//        the 16B .v4.f32 form is rejected by ptxas on sm_103a). Keeps the
//        6MB tag table L2-resident despite the 320MB store churn.
//      - video-row loads : __ldcs (read-once, evict-first)
//      - output stream   : __stcs (evict-first)
// Cursor lifecycle per replay: 0 -> K1 fills -> K2 reads + resets (sole point).

#define D_DIM    768
#define T_DIM    2000
#define V_DIM    20000
#define BIN_CAP  64       // edges/video ~ Poisson(10); P(>64) ~ 0

__device__ int      g_cursor[V_DIM];            // zeroed at module load
__device__ unsigned g_edges [V_DIM * BIN_CAP];  // bit15 = isPos, low bits = tag

// 32-byte evict_last gather: 8 floats per lane per instruction.
struct f8 { float x0,x1,x2,x3,x4,x5,x6,x7; };
__device__ __forceinline__ f8 ldg_el32(const float* p) {
    unsigned long long a, b, c, d;
    asm("ld.global.nc.L2::evict_last.v4.b64 {%0,%1,%2,%3}, [%4];"
        : "=l"(a), "=l"(b), "=l"(c), "=l"(d) : "l"(p));
    f8 r;
    r.x0 = __uint_as_float((unsigned)a); r.x1 = __uint_as_float((unsigned)(a >> 32));
    r.x2 = __uint_as_float((unsigned)b); r.x3 = __uint_as_float((unsigned)(b >> 32));
    r.x4 = __uint_as_float((unsigned)c); r.x5 = __uint_as_float((unsigned)(c >> 32));
    r.x6 = __uint_as_float((unsigned)d); r.x7 = __uint_as_float((unsigned)(d >> 32));
    return r;
}

// ---------------------------------------------------------------------------
__global__ void scatter_kernel(const int* __restrict__ pos_src,
                               const int* __restrict__ pos_dst,
                               const int* __restrict__ neg_src,
                               const int* __restrict__ neg_dst,
                               int nPos, int nTot) {
    int i = blockIdx.x * blockDim.x + threadIdx.x;
    if (i < nTot) {
        int v; unsigned enc;
        if (i < nPos) { v = pos_dst[i];        enc = (unsigned)pos_src[i] | 0x8000u; }
        else          { v = neg_dst[i - nPos]; enc = (unsigned)neg_src[i - nPos]; }
        int slot = atomicAdd(&g_cursor[v], 1);
        if (slot < BIN_CAP)
            g_edges[v * BIN_CAP + slot] = enc;
    }
}

// ---------------------------------------------------------------------------
// One block per video. Zero a 16KB smem image of (cls row, labels row),
// compute the ~10 edge dots into it, stream both rows out.
// Data layout per warp: lane owns 8-float chunks at float offset
//   j*256 + lane*8   for j = 0..2   (3 chunks x 8 floats = 24 floats/lane)
// ---------------------------------------------------------------------------
__global__ __launch_bounds__(256, 4) void fused_kernel(
    const float* __restrict__ h_tag,
    const float* __restrict__ h_video,
    float*       __restrict__ cls,
    float*       __restrict__ labels)
{
    __shared__ float s_row[2 * T_DIM];   // [0:2000) cls, [2000:4000) labels
    __shared__ int   s_n;

    const int v    = blockIdx.x;
    const int tid  = threadIdx.x;
    const int lane = tid & 31;
    const int warp = tid >> 5;

    if (tid == 0) {
        int c = g_cursor[v];
        s_n = (c > BIN_CAP) ? BIN_CAP : c;
        g_cursor[v] = 0;                 // sole reset point (next replay)
    }
    float4* s_vec = reinterpret_cast<float4*>(s_row);
#pragma unroll
    for (int i = tid; i < 2 * T_DIM / 4; i += 256)
        s_vec[i] = make_float4(0.f, 0.f, 0.f, 0.f);
    __syncthreads();

    const int n = s_n;

    if (n > 0) {
        // video row -> per-warp registers (streaming, evict-first)
        const float4* b = reinterpret_cast<const float4*>(h_video + (size_t)v * D_DIM);
        // chunk j floats [j*256 + lane*8 .. +8) = float4s (j*64 + lane*2, +1)
        float4 v00 = __ldcs(b + 0 * 64 + lane * 2);
        float4 v01 = __ldcs(b + 0 * 64 + lane * 2 + 1);
        float4 v10 = __ldcs(b + 1 * 64 + lane * 2);
        float4 v11 = __ldcs(b + 1 * 64 + lane * 2 + 1);
        float4 v20 = __ldcs(b + 2 * 64 + lane * 2);
        float4 v21 = __ldcs(b + 2 * 64 + lane * 2 + 1);

        const unsigned* elist = g_edges + (size_t)v * BIN_CAP;

        // warp-per-edge: gather tag row with evict_last (protect 6MB table)
        for (int e = warp; e < n; e += 8) {
            unsigned enc = elist[e];
            int t = (int)(enc & 0x7fffu);
            const float* a = h_tag + (size_t)t * D_DIM;

            f8 a0 = ldg_el32(a + 0 * 256 + lane * 8);
            f8 a1 = ldg_el32(a + 1 * 256 + lane * 8);
            f8 a2 = ldg_el32(a + 2 * 256 + lane * 8);

            float acc;
            acc  = a0.x0 * v00.x + a0.x1 * v00.y + a0.x2 * v00.z + a0.x3 * v00.w;
            acc += a0.x4 * v01.x + a0.x5 * v01.y + a0.x6 * v01.z + a0.x7 * v01.w;
            acc += a1.x0 * v10.x + a1.x1 * v10.y + a1.x2 * v10.z + a1.x3 * v10.w;
            acc += a1.x4 * v11.x + a1.x5 * v11.y + a1.x6 * v11.z + a1.x7 * v11.w;
            acc += a2.x0 * v20.x + a2.x1 * v20.y + a2.x2 * v20.z + a2.x3 * v20.w;
            acc += a2.x4 * v21.x + a2.x5 * v21.y + a2.x6 * v21.z + a2.x7 * v21.w;

#pragma unroll
            for (int off = 16; off > 0; off >>= 1)
                acc += __shfl_xor_sync(0xffffffffu, acc, off);

            if (lane == 0) {
                atomicAdd(&s_row[t], acc);
                if (enc & 0x8000u) atomicAdd(&s_row[T_DIM + t], 1.0f);
            }
        }
    }
    __syncthreads();

    // stream both complete rows out (evict-first; zeros + scores together)
    float4* out_cls = reinterpret_cast<float4*>(cls    + (size_t)v * T_DIM);
    float4* out_lab = reinterpret_cast<float4*>(labels + (size_t)v * T_DIM);
#pragma unroll
    for (int i = tid; i < T_DIM / 4; i += 256) {
        __stcs(&out_cls[i], s_vec[i]);
        __stcs(&out_lab[i], s_vec[i + T_DIM / 4]);
    }
}

// ---------------------------------------------------------------------------
extern "C" void kernel_launch(void* const* d_in, const int* in_sizes, int n_in,
                              void* d_out, int out_size)
{
    const float* h_tag   = (const float*)d_in[0];
    const float* h_video = (const float*)d_in[1];
    const int*   pos_src = (const int*)d_in[2];
    const int*   pos_dst = (const int*)d_in[3];
    const int*   neg_src = (const int*)d_in[4];
    const int*   neg_dst = (const int*)d_in[5];

    const int nPos = in_sizes[2];
    const int nNeg = in_sizes[4];
    const int nTot = nPos + nNeg;

    float* cls    = (float*)d_out;
    long long vt  = (long long)out_size / 2;
    float* labels = cls + vt;

    // 1) bin edges by video
    scatter_kernel<<<(nTot + 255) / 256, 256>>>(pos_src, pos_dst, neg_src, neg_dst,
                                                nPos, nTot);

    // 2) fused: dots + full output stream in one kernel
    fused_kernel<<<V_DIM, 256>>>(h_tag, h_video, cls, labels);
}

// round 12
// speedup vs baseline: 1.7051x; 1.7051x over previous
#include <cuda_runtime.h>
#include <cstdint>

// T = 2000 tags, V = 20000 videos, D = 768, E_POS = E_NEG = 100000
// Output layout: [cls_score (V*T f32), labels (V*T f32)]
//
// R12 (serial phases, each tuned to its roof):
//   K1 zero_kernel   : 320MB evict-first stream (proven 44.8us, DRAM-bound)
//   K2 scatter_kernel: bin edges by (tag, sub) with sub = edge_idx & 7.
//                      16000 counters -> ~12.5 atomics each (kills the 13us
//                      per-address L2 atomic-ALU serialization -> ~4us)
//   K3 edge_kernel   : block per tag, warp w owns sub-bin w exclusively.
//                      Tag row in 24 regs; video row in two 3xfloat4 batches
//                      FMA'd immediately (low regs -> 5 blocks/SM, high MLP
//                      from resident warps instead of the 78-reg prefetch
//                      that throttled R3/R9 to 3 blocks/SM).

#define D_DIM    768
#define T_DIM    2000
#define BIN_SUB  8
#define SUB_CAP  48      // Poisson(12.5)/sub-bin; P(>48) ~ 1e-11

__device__ int      g_cursor[T_DIM * BIN_SUB];            // zero at module load
__device__ unsigned g_edges [T_DIM * BIN_SUB * SUB_CAP];  // bit31=isPos, low=dst

// ---------------------------------------------------------------------------
__global__ void zero_kernel(float4* __restrict__ out, long long nvec) {
    long long i = (long long)blockIdx.x * blockDim.x + threadIdx.x;
    if (i < nvec)
        __stcs(&out[i], make_float4(0.f, 0.f, 0.f, 0.f));
}

// ---------------------------------------------------------------------------
__global__ void scatter_kernel(const int* __restrict__ pos_src,
                               const int* __restrict__ pos_dst,
                               const int* __restrict__ neg_src,
                               const int* __restrict__ neg_dst,
                               int nPos, int nTot) {
    int i = blockIdx.x * blockDim.x + threadIdx.x;
    if (i < nTot) {
        int t; unsigned enc;
        if (i < nPos) { t = pos_src[i];        enc = (unsigned)pos_dst[i] | 0x80000000u; }
        else          { t = neg_src[i - nPos]; enc = (unsigned)neg_dst[i - nPos]; }
        int cidx = t * BIN_SUB + (i & (BIN_SUB - 1));
        int slot = atomicAdd(&g_cursor[cidx], 1);
        if (slot < SUB_CAP)
            g_edges[cidx * SUB_CAP + slot] = enc;
    }
}

// ---------------------------------------------------------------------------
// Block per tag; warp w owns sub-bin w (exclusive -> race-free cursor
// read+reset within the warp). Tag row: smem -> 24 registers. Per edge:
// two batches of 3 float4 video loads, FMA'd immediately (keeps ~48 regs).
// ---------------------------------------------------------------------------
__global__ __launch_bounds__(256) void edge_kernel(
    const float* __restrict__ h_tag,
    const float* __restrict__ h_video,
    float*       __restrict__ cls,
    float*       __restrict__ labels)
{
    __shared__ float4 stag[D_DIM / 4];   // 3KB tag row

    const int t   = blockIdx.x;
    const int tid = threadIdx.x;

    if (tid < D_DIM / 4)
        stag[tid] = reinterpret_cast<const float4*>(h_tag + (size_t)t * D_DIM)[tid];
    __syncthreads();

    const int lane = tid & 31;
    const int warp = tid >> 5;           // == sub-bin index (8 warps)

    // tag row -> registers
    float4 ta0 = stag[lane +   0];
    float4 ta1 = stag[lane +  32];
    float4 ta2 = stag[lane +  64];
    float4 ta3 = stag[lane +  96];
    float4 ta4 = stag[lane + 128];
    float4 ta5 = stag[lane + 160];

    const int cidx = t * BIN_SUB + warp;
    int n = 0;
    if (lane == 0) {
        n = g_cursor[cidx];
        g_cursor[cidx] = 0;              // warp-exclusive reset (next replay)
    }
    n = __shfl_sync(0xffffffffu, n, 0);
    if (n > SUB_CAP) n = SUB_CAP;

    const unsigned* elist = g_edges + (size_t)cidx * SUB_CAP;

    for (int e = 0; e < n; e++) {
        unsigned enc = elist[e];
        int d = (int)(enc & 0x7fffffffu);
        const float4* b = reinterpret_cast<const float4*>(h_video + (size_t)d * D_DIM);

        // batch 1: 3 independent loads, then FMAs
        float4 b0 = __ldg(b + lane +   0);
        float4 b1 = __ldg(b + lane +  32);
        float4 b2 = __ldg(b + lane +  64);
        float acc;
        acc  = ta0.x * b0.x + ta0.y * b0.y + ta0.z * b0.z + ta0.w * b0.w;
        acc += ta1.x * b1.x + ta1.y * b1.y + ta1.z * b1.z + ta1.w * b1.w;
        acc += ta2.x * b2.x + ta2.y * b2.y + ta2.z * b2.z + ta2.w * b2.w;

        // batch 2: reuse registers
        float4 b3 = __ldg(b + lane +  96);
        float4 b4 = __ldg(b + lane + 128);
        float4 b5 = __ldg(b + lane + 160);
        acc += ta3.x * b3.x + ta3.y * b3.y + ta3.z * b3.z + ta3.w * b3.w;
        acc += ta4.x * b4.x + ta4.y * b4.y + ta4.z * b4.z + ta4.w * b4.w;
        acc += ta5.x * b5.x + ta5.y * b5.y + ta5.z * b5.z + ta5.w * b5.w;

#pragma unroll
        for (int off = 16; off > 0; off >>= 1)
            acc += __shfl_xor_sync(0xffffffffu, acc, off);

        if (lane == 0) {
            size_t cell = (size_t)d * T_DIM + (size_t)t;
            atomicAdd(&cls[cell], acc);
            if (enc & 0x80000000u) atomicAdd(&labels[cell], 1.0f);
        }
    }
}

// ---------------------------------------------------------------------------
extern "C" void kernel_launch(void* const* d_in, const int* in_sizes, int n_in,
                              void* d_out, int out_size)
{
    const float* h_tag   = (const float*)d_in[0];
    const float* h_video = (const float*)d_in[1];
    const int*   pos_src = (const int*)d_in[2];
    const int*   pos_dst = (const int*)d_in[3];
    const int*   neg_src = (const int*)d_in[4];
    const int*   neg_dst = (const int*)d_in[5];

    const int nPos = in_sizes[2];
    const int nNeg = in_sizes[4];
    const int nTot = nPos + nNeg;

    float* cls    = (float*)d_out;
    long long vt  = (long long)out_size / 2;
    float* labels = cls + vt;

    // 1) zero the output (DRAM-write-bound)
    {
        long long nvec = (long long)out_size / 4;
        long long blocks = (nvec + 255) / 256;
        zero_kernel<<<(unsigned)blocks, 256>>>((float4*)d_out, nvec);
    }

    // 2) sub-binned scatter (bins land hot in L2 for the edge kernel)
    scatter_kernel<<<(nTot + 255) / 256, 256>>>(pos_src, pos_dst, neg_src, neg_dst,
                                                nPos, nTot);

    // 3) edge gather + direct scatter-add
    edge_kernel<<<T_DIM, 256>>>(h_tag, h_video, cls, labels);
}